// round 5
// baseline (speedup 1.0000x reference)
#include <cuda_runtime.h>
#include <math.h>

#define NU 50000
#define NI 50000
#define NN 100000
#define NE 1600000
#define NP 200000
#define H  64
#define SCAN_NBLK ((NN + 1023) / 1024)   // 98

// ---------------- device scratch ----------------
__device__ int   g_ocnt[NN];
__device__ int   g_icnt[NN];
__device__ float g_onorm[NN];
__device__ float g_innorm[NN];
__device__ int   g_off[NN];
__device__ int   g_cur[NN];
__device__ int   g_bsum[SCAN_NBLK];
__device__ int   g_boff[SCAN_NBLK];
__device__ int   g_csrc[NE];
__device__ float g_e0[(size_t)NN * H];
__device__ float g_agg0[(size_t)NN * H];
__device__ float g_xu[(size_t)NU * H];
__device__ float g_xi[(size_t)NI * H];

// ---------------- shared-memory GEMM body (48KB buffer) ----------------
// C[M x 64] = A[M x K] @ W[K x 64]; 128x64 tile, 256 thr, 8x4 reg tile.
__device__ __forceinline__ void gemm_body(
    int gb, char* sh,
    const float* __restrict__ A1, const float* __restrict__ W1, const float* __restrict__ b1,
    float* __restrict__ C1, int M1,
    const float* __restrict__ A2, const float* __restrict__ W2, const float* __restrict__ b2,
    float* __restrict__ C2, int M2,
    int K, int doRelu, int nb1)
{
    float (*Ws)[64] = (float(*)[64])sh;                       // [128][64] = 32KB
    float (*As)[16][128] = (float(*)[16][128])(sh + 32768);   // [2][16][128] = 16KB

    const float* A; const float* W; const float* bias; float* C; int M, bm0;
    if (gb < nb1) {
        A = A1; W = W1; bias = b1; C = C1; M = M1; bm0 = gb * 128;
    } else {
        A = A2; W = W2; bias = b2; C = C2; M = M2; bm0 = (gb - nb1) * 128;
    }

    int t = threadIdx.x;

    for (int i = t; i < K * 16; i += 256) {
        int k = i >> 4, q = i & 15;
        *(float4*)&Ws[k][q * 4] = *(const float4*)(W + (size_t)k * 64 + q * 4);
    }

    int lrow = t >> 1;
    int lq = (t & 1) * 8;
    int row = bm0 + lrow;
    bool rv = row < M;
    const float* Ar = A + (size_t)row * K;

    float4 p0 = make_float4(0.f, 0.f, 0.f, 0.f), p1 = p0;

#define FETCH(k0) do { \
    if (rv) { p0 = *(const float4*)(Ar + (k0) + lq); p1 = *(const float4*)(Ar + (k0) + lq + 4); } \
} while (0)
#define STAGE(buf) do { \
    As[buf][lq + 0][lrow] = p0.x; As[buf][lq + 1][lrow] = p0.y; \
    As[buf][lq + 2][lrow] = p0.z; As[buf][lq + 3][lrow] = p0.w; \
    As[buf][lq + 4][lrow] = p1.x; As[buf][lq + 5][lrow] = p1.y; \
    As[buf][lq + 6][lrow] = p1.z; As[buf][lq + 7][lrow] = p1.w; \
} while (0)

    FETCH(0);
    STAGE(0);
    __syncthreads();

    float acc[8][4];
#pragma unroll
    for (int i = 0; i < 8; i++)
#pragma unroll
        for (int j = 0; j < 4; j++) acc[i][j] = 0.f;

    int tx = t & 15;
    int ty = t >> 4;
    int nt = K >> 4;

    for (int tile = 0; tile < nt; tile++) {
        int buf = tile & 1;
        if (tile + 1 < nt) FETCH((tile + 1) << 4);

#pragma unroll
        for (int k = 0; k < 16; k++) {
            float4 b  = *(const float4*)&Ws[(tile << 4) + k][tx * 4];
            float4 x0 = *(const float4*)&As[buf][k][ty * 8];
            float4 x1 = *(const float4*)&As[buf][k][ty * 8 + 4];
            acc[0][0] += x0.x * b.x; acc[0][1] += x0.x * b.y; acc[0][2] += x0.x * b.z; acc[0][3] += x0.x * b.w;
            acc[1][0] += x0.y * b.x; acc[1][1] += x0.y * b.y; acc[1][2] += x0.y * b.z; acc[1][3] += x0.y * b.w;
            acc[2][0] += x0.z * b.x; acc[2][1] += x0.z * b.y; acc[2][2] += x0.z * b.z; acc[2][3] += x0.z * b.w;
            acc[3][0] += x0.w * b.x; acc[3][1] += x0.w * b.y; acc[3][2] += x0.w * b.z; acc[3][3] += x0.w * b.w;
            acc[4][0] += x1.x * b.x; acc[4][1] += x1.x * b.y; acc[4][2] += x1.x * b.z; acc[4][3] += x1.x * b.w;
            acc[5][0] += x1.y * b.x; acc[5][1] += x1.y * b.y; acc[5][2] += x1.y * b.z; acc[5][3] += x1.y * b.w;
            acc[6][0] += x1.z * b.x; acc[6][1] += x1.z * b.y; acc[6][2] += x1.z * b.z; acc[6][3] += x1.z * b.w;
            acc[7][0] += x1.w * b.x; acc[7][1] += x1.w * b.y; acc[7][2] += x1.w * b.z; acc[7][3] += x1.w * b.w;
        }

        if (tile + 1 < nt) {
            __syncthreads();
            STAGE((tile + 1) & 1);
            __syncthreads();
        }
    }

    float bvals[4] = {0.f, 0.f, 0.f, 0.f};
    if (bias) {
#pragma unroll
        for (int j = 0; j < 4; j++) bvals[j] = bias[tx * 4 + j];
    }

#pragma unroll
    for (int r = 0; r < 8; r++) {
        int orow = bm0 + ty * 8 + r;
        if (orow < M) {
            float4 v;
            v.x = acc[r][0] + bvals[0];
            v.y = acc[r][1] + bvals[1];
            v.z = acc[r][2] + bvals[2];
            v.w = acc[r][3] + bvals[3];
            if (doRelu) {
                v.x = fmaxf(v.x, 0.f); v.y = fmaxf(v.y, 0.f);
                v.z = fmaxf(v.z, 0.f); v.w = fmaxf(v.w, 0.f);
            }
            *(float4*)(C + (size_t)orow * 64 + tx * 4) = v;
        }
    }
#undef FETCH
#undef STAGE
}

// ---------------- fused CSR-stage + GEMM-chunk co-kernel ----------------
// stage: 0=clear 1=degree 2=scan1 3=scan2 4=scan3 5=fill
__global__ void __launch_bounds__(256) csr_gemm_kernel(
    int stage, int nGemm, int gemmStart,
    const int* __restrict__ esrc, const int* __restrict__ edst,
    const float* __restrict__ A1, const float* __restrict__ W1, const float* __restrict__ b1,
    float* __restrict__ C1, int M1,
    const float* __restrict__ A2, const float* __restrict__ W2, const float* __restrict__ b2,
    float* __restrict__ C2, int M2,
    int K, int doRelu, int nb1, int nbTot)
{
    __shared__ char sh[49152];
    int tid = threadIdx.x;

    if ((int)blockIdx.x < nGemm) {
        int gb = gemmStart + blockIdx.x;
        if (gb < nbTot)
            gemm_body(gb, sh, A1, W1, b1, C1, M1, A2, W2, b2, C2, M2, K, doRelu, nb1);
        return;
    }
    int cb = blockIdx.x - nGemm;

    if (stage == 0) {
        int i = cb * 256 + tid;
        if (i < NN) { g_ocnt[i] = 0; g_icnt[i] = 0; }
    } else if (stage == 1) {
        int e = cb * 256 + tid;
        if (e < NE) {
            atomicAdd(&g_ocnt[esrc[e]], 1);
            atomicAdd(&g_icnt[edst[e]], 1);
        }
    } else if (stage == 2) {
        // scan1: 256 threads, 4 elems each (1024 per block)
        int base = cb * 1024 + tid * 4;
        int v0 = (base + 0 < NN) ? g_icnt[base + 0] : 0;
        int v1 = (base + 1 < NN) ? g_icnt[base + 1] : 0;
        int v2 = (base + 2 < NN) ? g_icnt[base + 2] : 0;
        int v3 = (base + 3 < NN) ? g_icnt[base + 3] : 0;
        int s1 = v0, s2 = v0 + v1, s3 = v0 + v1 + v2, s = s3 + v3;
        int lane = tid & 31, wp = tid >> 5;
        int incl = s;
#pragma unroll
        for (int o = 1; o < 32; o <<= 1) {
            int n = __shfl_up_sync(0xffffffffu, incl, o);
            if (lane >= o) incl += n;
        }
        int* wsum = (int*)sh;
        if (lane == 31) wsum[wp] = incl;
        __syncthreads();
        int wbase = 0;
        for (int k = 0; k < wp; k++) wbase += wsum[k];
        int et = wbase + incl - s;
        if (base + 0 < NN) g_off[base + 0] = et;
        if (base + 1 < NN) g_off[base + 1] = et + s1;
        if (base + 2 < NN) g_off[base + 2] = et + s2;
        if (base + 3 < NN) g_off[base + 3] = et + s3;
        if (tid == 255) g_bsum[cb] = wbase + incl;
    } else if (stage == 3) {
        // scan2: single csr block over SCAN_NBLK sums
        int v = (tid < SCAN_NBLK) ? g_bsum[tid] : 0;
        int lane = tid & 31, wp = tid >> 5;
        int incl = v;
#pragma unroll
        for (int o = 1; o < 32; o <<= 1) {
            int n = __shfl_up_sync(0xffffffffu, incl, o);
            if (lane >= o) incl += n;
        }
        int* wsum = (int*)sh;
        if (lane == 31) wsum[wp] = incl;
        __syncthreads();
        int wbase = 0;
        for (int k = 0; k < wp; k++) wbase += wsum[k];
        if (tid < SCAN_NBLK) g_boff[tid] = wbase + incl - v;
    } else if (stage == 4) {
        int i = cb * 256 + tid;
        if (i < NN) {
            int o = g_off[i] + g_boff[i >> 10];
            g_off[i] = o;
            g_cur[i] = o;
            g_onorm[i]  = rsqrtf(fmaxf((float)g_ocnt[i], 1.0f));
            g_innorm[i] = rsqrtf(fmaxf((float)g_icnt[i], 1.0f));
        }
    } else {
        int e = cb * 256 + tid;
        if (e < NE) {
            int pos = atomicAdd(&g_cur[edst[e]], 1);
            g_csrc[pos] = esrc[e];
        }
    }
}

// ---------------- plain dual GEMM (second GEMM pass) ----------------
__global__ void __launch_bounds__(256) gemm_dual(
    const float* __restrict__ A1, const float* __restrict__ W1, const float* __restrict__ b1,
    float* __restrict__ C1, int M1,
    const float* __restrict__ A2, const float* __restrict__ W2, const float* __restrict__ b2,
    float* __restrict__ C2, int M2,
    int K, int doRelu, int nb1)
{
    __shared__ char sh[49152];
    gemm_body(blockIdx.x, sh, A1, W1, b1, C1, M1, A2, W2, b2, C2, M2, K, doRelu, nb1);
}

// ---------------- GCN layer 1: gather (warp per node) ----------------
__global__ void gather1_kernel() {
    int gw = (blockIdx.x * blockDim.x + threadIdx.x) >> 5;
    int lane = threadIdx.x & 31;
    if (gw >= NN) return;
    int start = g_off[gw];
    int deg = g_icnt[gw];
    float a0 = 0.f, a1 = 0.f;
    for (int j0 = 0; j0 < deg; j0 += 32) {
        int n = min(32, deg - j0);
        int idx = 0; float w = 0.f;
        if (lane < n) { idx = g_csrc[start + j0 + lane]; w = g_onorm[idx]; }
#pragma unroll 4
        for (int jj = 0; jj < n; jj++) {
            int   s  = __shfl_sync(0xffffffffu, idx, jj);
            float wv = __shfl_sync(0xffffffffu, w, jj);
            const float* r = g_e0 + (size_t)s * 64;
            a0 += wv * r[lane];
            a1 += wv * r[lane + 32];
        }
    }
    float inn = g_innorm[gw];
    g_agg0[(size_t)gw * 64 + lane]      = a0 * inn;
    g_agg0[(size_t)gw * 64 + lane + 32] = a1 * inn;
}

// ---------------- GCN layer 2 + final combine fused ----------------
__global__ void gather2_final_kernel(const float* __restrict__ side, float* __restrict__ out) {
    int gw = (blockIdx.x * blockDim.x + threadIdx.x) >> 5;
    int lane = threadIdx.x & 31;
    if (gw >= NN) return;
    int start = g_off[gw];
    int deg = g_icnt[gw];
    float a0 = 0.f, a1 = 0.f;
    for (int j0 = 0; j0 < deg; j0 += 32) {
        int n = min(32, deg - j0);
        int idx = 0; float w = 0.f;
        if (lane < n) { idx = g_csrc[start + j0 + lane]; w = g_onorm[idx]; }
#pragma unroll 4
        for (int jj = 0; jj < n; jj++) {
            int   s  = __shfl_sync(0xffffffffu, idx, jj);
            float wv = __shfl_sync(0xffffffffu, w, jj);
            const float* r = g_agg0 + (size_t)s * 64;
            a0 += wv * r[lane];
            a1 += wv * r[lane + 32];
        }
    }
    float inn3 = g_innorm[gw] * (1.0f / 3.0f);
    size_t base = (size_t)gw * 64;
    float r0v = g_e0[base + lane]      + 0.5f * g_agg0[base + lane]      + inn3 * a0;
    float r1v = g_e0[base + lane + 32] + 0.5f * g_agg0[base + lane + 32] + inn3 * a1;
    if (gw >= NU) {
        size_t sb = (size_t)(gw - NU) * 64;
        r0v += side[sb + lane];
        r1v += side[sb + lane + 32];
    }
    out[base + lane]      = r0v;
    out[base + lane + 32] = r1v;
}

// ---------------- decode epilogue ----------------
__global__ void decode_kernel(const float* __restrict__ Tf, const float* __restrict__ Tcf,
                              const float* __restrict__ W1, const float* __restrict__ W2,
                              const int* __restrict__ userId, const int* __restrict__ posId,
                              const int* __restrict__ negId,
                              float* __restrict__ of, float* __restrict__ ocf) {
    __shared__ float w2s[64];
    __shared__ float w1l[64];
    int t = threadIdx.x;
    if (t < 64) {
        w2s[t] = W2[t];
        w1l[t] = W1[128 * 64 + t];
    }
    __syncthreads();

    int warp = t >> 5, lane = t & 31;
    int pair = blockIdx.x * 8 + warp;
    if (pair >= NP) return;

    int u  = userId[pair];
    int p  = posId[pair];
    int ng = negId[pair];

    float u0 = g_xu[(size_t)u * 64 + lane],   u1 = g_xu[(size_t)u * 64 + lane + 32];
    float p0 = g_xi[(size_t)p * 64 + lane],   p1 = g_xi[(size_t)p * 64 + lane + 32];
    float n0 = g_xi[(size_t)ng * 64 + lane],  n1 = g_xi[(size_t)ng * 64 + lane + 32];
    float wl0 = w1l[lane], wl1 = w1l[lane + 32];
    float w20 = w2s[lane], w21 = w2s[lane + 32];

    float tfp = Tf[pair],  tfn = Tf[pair + NP];
    float tcp = Tcf[pair], tcn = Tcf[pair + NP];

    auto combo = [&](float j0, float j1, float T) -> float {
        float x0 = u0 + j0 + T * wl0;
        float x1 = u1 + j1 + T * wl1;
        float e0 = x0 > 0.f ? x0 : (expf(x0) - 1.0f);
        float e1 = x1 > 0.f ? x1 : (expf(x1) - 1.0f);
        float s = e0 * w20 + e1 * w21;
        s += __shfl_down_sync(0xffffffffu, s, 16);
        s += __shfl_down_sync(0xffffffffu, s, 8);
        s += __shfl_down_sync(0xffffffffu, s, 4);
        s += __shfl_down_sync(0xffffffffu, s, 2);
        s += __shfl_down_sync(0xffffffffu, s, 1);
        return s;
    };

    float rf_p = combo(p0, p1, tfp);
    float rf_n = combo(n0, n1, tfn);
    float rc_p = combo(p0, p1, tcp);
    float rc_n = combo(n0, n1, tcn);

    if (lane == 0) {
        of[pair]       = rf_p;
        of[pair + NP]  = rf_n;
        ocf[pair]      = rc_p;
        ocf[pair + NP] = rc_n;
    }
}

// ---------------- launch ----------------
extern "C" void kernel_launch(void* const* d_in, const int* in_sizes, int n_in,
                              void* d_out, int out_size) {
    const float* userF = (const float*)d_in[0];
    const float* itemF = (const float*)d_in[1];
    const float* side  = (const float*)d_in[2];
    const float* Tf    = (const float*)d_in[3];
    const float* Tcf   = (const float*)d_in[4];
    const float* Wu    = (const float*)d_in[5];
    const float* bu    = (const float*)d_in[6];
    const float* Wi    = (const float*)d_in[7];
    const float* bi    = (const float*)d_in[8];
    const float* W1    = (const float*)d_in[9];
    const float* b1    = (const float*)d_in[10];
    const float* W2    = (const float*)d_in[11];
    const int* esrc    = (const int*)d_in[12];
    const int* edst    = (const int*)d_in[13];
    const int* userId  = (const int*)d_in[14];
    const int* posId   = (const int*)d_in[15];
    const int* negId   = (const int*)d_in[16];

    float* out   = (float*)d_out;
    float* outI  = out + (size_t)NU * H;
    float* outLF = out + (size_t)NN * H;
    float* outLC = outLF + 2 * NP;

    float *pe0, *pxu, *pxi;
    cudaGetSymbolAddress((void**)&pe0, g_e0);
    cudaGetSymbolAddress((void**)&pxu, g_xu);
    cudaGetSymbolAddress((void**)&pxi, g_xi);

    int nb1 = (NU + 127) / 128;            // 391
    int nb2 = (NI + 127) / 128;            // 391
    int nbTot = nb1 + nb2;                 // 782

    // CSR stages co-scheduled with chunks of the input-embedding GEMM.
    // csr block counts per stage:
    const int csrBlocks[6] = {(NN + 255) / 256, (NE + 255) / 256, SCAN_NBLK, 1,
                              (NN + 255) / 256, (NE + 255) / 256};
    // gemm chunk sizes (sum = nbTot)
    const int chunk[6] = {40, 240, 100, 80, 40, 282};

    int gs = 0;
    for (int st = 0; st < 6; st++) {
        int ng = chunk[st];
        csr_gemm_kernel<<<ng + csrBlocks[st], 256>>>(
            st, ng, gs, esrc, edst,
            userF, Wu, bu, pe0, NU,
            itemF, Wi, bi, pe0 + (size_t)NU * H, NI,
            128, 1, nb1, nbTot);
        gs += ng;
    }

    // GCN layers
    gather1_kernel<<<(NN * 32 + 255) / 256, 256>>>();
    gather2_final_kernel<<<(NN * 32 + 255) / 256, 256>>>(side, out);

    // per-node decode transforms
    gemm_dual<<<nbTot, 256>>>(out,  W1,           b1,      pxu, NU,
                              outI, W1 + 64 * 64, nullptr, pxi, NI,
                              64, 0, nb1);

    // decode epilogue
    decode_kernel<<<(NP + 7) / 8, 256>>>(Tf, Tcf, W1, W2, userId, posId, negId, outLF, outLC);
}

// round 6
// speedup vs baseline: 1.0751x; 1.0751x over previous
#include <cuda_runtime.h>
#include <math.h>

#define NU 50000
#define NI 50000
#define NN 100000
#define NE 1600000
#define NP 200000
#define H  64
#define SCAN_NBLK ((NN + 1023) / 1024)   // 98

// ---------------- device scratch ----------------
__device__ int   g_ocnt[NN];
__device__ int   g_icnt[NN];
__device__ float g_onorm[NN];
__device__ float g_innorm[NN];
__device__ int   g_off[NN];
__device__ int   g_cur[NN];
__device__ int   g_bsum[SCAN_NBLK];
__device__ int   g_boff[SCAN_NBLK];
__device__ int   g_csrc[NE];
__device__ float g_e0[(size_t)NN * H];
__device__ float g_agg0[(size_t)NN * H];
__device__ float g_xu[(size_t)NU * H];
__device__ float g_xi[(size_t)NI * H];

// ---------------- lean GEMM body: 24.6KB smem, double-buffered A and W ----------------
// C[M x 64] = A[M x K] @ W[K x 64]; 128x64 tile, 256 thr, 8x4 reg tile.
// sh layout: Ws[2][16][64] at 0 (8KB), As[2][16][128] at 8192 (16KB)
__device__ __forceinline__ void gemm_body(
    int gb, char* sh,
    const float* __restrict__ A1, const float* __restrict__ W1, const float* __restrict__ b1,
    float* __restrict__ C1, int M1,
    const float* __restrict__ A2, const float* __restrict__ W2, const float* __restrict__ b2,
    float* __restrict__ C2, int M2,
    int K, int doRelu, int nb1)
{
    float (*Ws)[16][64]  = (float(*)[16][64])sh;
    float (*As)[16][128] = (float(*)[16][128])(sh + 8192);

    const float* A; const float* W; const float* bias; float* C; int M, bm0;
    if (gb < nb1) {
        A = A1; W = W1; bias = b1; C = C1; M = M1; bm0 = gb * 128;
    } else {
        A = A2; W = W2; bias = b2; C = C2; M = M2; bm0 = (gb - nb1) * 128;
    }

    int t = threadIdx.x;

    // W tile mapping: 256 threads load 16x16 float4 (one each)
    int wk = t >> 4;          // k-row within tile
    int wc = t & 15;          // col quad

    // A staging: 2 threads per row, each covers 8 consecutive k
    int lrow = t >> 1;
    int lq = (t & 1) * 8;
    int row = bm0 + lrow;
    bool rv = row < M;
    const float* Ar = A + (size_t)row * K;

    float4 p0 = make_float4(0.f, 0.f, 0.f, 0.f), p1 = p0, wv = p0;

#define FETCHA(k0) do { \
    if (rv) { p0 = *(const float4*)(Ar + (k0) + lq); p1 = *(const float4*)(Ar + (k0) + lq + 4); } \
} while (0)
#define FETCHW(k0) do { wv = *(const float4*)(W + (size_t)((k0) + wk) * 64 + wc * 4); } while (0)
#define STAGEA(buf) do { \
    As[buf][lq + 0][lrow] = p0.x; As[buf][lq + 1][lrow] = p0.y; \
    As[buf][lq + 2][lrow] = p0.z; As[buf][lq + 3][lrow] = p0.w; \
    As[buf][lq + 4][lrow] = p1.x; As[buf][lq + 5][lrow] = p1.y; \
    As[buf][lq + 6][lrow] = p1.z; As[buf][lq + 7][lrow] = p1.w; \
} while (0)
#define STAGEW(buf) do { *(float4*)&Ws[buf][wk][wc * 4] = wv; } while (0)

    FETCHA(0); FETCHW(0);
    STAGEA(0); STAGEW(0);
    __syncthreads();

    float acc[8][4];
#pragma unroll
    for (int i = 0; i < 8; i++)
#pragma unroll
        for (int j = 0; j < 4; j++) acc[i][j] = 0.f;

    int tx = t & 15;
    int ty = t >> 4;
    int nt = K >> 4;

    for (int tile = 0; tile < nt; tile++) {
        int buf = tile & 1;
        if (tile + 1 < nt) { FETCHA((tile + 1) << 4); FETCHW((tile + 1) << 4); }

#pragma unroll
        for (int k = 0; k < 16; k++) {
            float4 b  = *(const float4*)&Ws[buf][k][tx * 4];
            float4 x0 = *(const float4*)&As[buf][k][ty * 8];
            float4 x1 = *(const float4*)&As[buf][k][ty * 8 + 4];
            acc[0][0] += x0.x * b.x; acc[0][1] += x0.x * b.y; acc[0][2] += x0.x * b.z; acc[0][3] += x0.x * b.w;
            acc[1][0] += x0.y * b.x; acc[1][1] += x0.y * b.y; acc[1][2] += x0.y * b.z; acc[1][3] += x0.y * b.w;
            acc[2][0] += x0.z * b.x; acc[2][1] += x0.z * b.y; acc[2][2] += x0.z * b.z; acc[2][3] += x0.z * b.w;
            acc[3][0] += x0.w * b.x; acc[3][1] += x0.w * b.y; acc[3][2] += x0.w * b.z; acc[3][3] += x0.w * b.w;
            acc[4][0] += x1.x * b.x; acc[4][1] += x1.x * b.y; acc[4][2] += x1.x * b.z; acc[4][3] += x1.x * b.w;
            acc[5][0] += x1.y * b.x; acc[5][1] += x1.y * b.y; acc[5][2] += x1.y * b.z; acc[5][3] += x1.y * b.w;
            acc[6][0] += x1.z * b.x; acc[6][1] += x1.z * b.y; acc[6][2] += x1.z * b.z; acc[6][3] += x1.z * b.w;
            acc[7][0] += x1.w * b.x; acc[7][1] += x1.w * b.y; acc[7][2] += x1.w * b.z; acc[7][3] += x1.w * b.w;
        }

        if (tile + 1 < nt) {
            __syncthreads();
            STAGEA((tile + 1) & 1);
            STAGEW((tile + 1) & 1);
            __syncthreads();
        }
    }

    float bvals[4] = {0.f, 0.f, 0.f, 0.f};
    if (bias) {
#pragma unroll
        for (int j = 0; j < 4; j++) bvals[j] = bias[tx * 4 + j];
    }

#pragma unroll
    for (int r = 0; r < 8; r++) {
        int orow = bm0 + ty * 8 + r;
        if (orow < M) {
            float4 v;
            v.x = acc[r][0] + bvals[0];
            v.y = acc[r][1] + bvals[1];
            v.z = acc[r][2] + bvals[2];
            v.w = acc[r][3] + bvals[3];
            if (doRelu) {
                v.x = fmaxf(v.x, 0.f); v.y = fmaxf(v.y, 0.f);
                v.z = fmaxf(v.z, 0.f); v.w = fmaxf(v.w, 0.f);
            }
            *(float4*)(C + (size_t)orow * 64 + tx * 4) = v;
        }
    }
#undef FETCHA
#undef FETCHW
#undef STAGEA
#undef STAGEW
}

// ---------------- fused edge-stage + GEMM-chunk co-kernel ----------------
// stage: 1=degree, 5=fill; edge blocks process 4 edges/thread via int4
__global__ void __launch_bounds__(256, 4) csr_gemm_kernel(
    int stage, int nGemm, int gemmStart,
    const int* __restrict__ esrc, const int* __restrict__ edst,
    const float* __restrict__ A1, const float* __restrict__ W1, const float* __restrict__ b1,
    float* __restrict__ C1, int M1,
    const float* __restrict__ A2, const float* __restrict__ W2, const float* __restrict__ b2,
    float* __restrict__ C2, int M2,
    int K, int doRelu, int nb1, int nbTot)
{
    __shared__ char sh[24576];
    int tid = threadIdx.x;

    if ((int)blockIdx.x < nGemm) {
        int gb = gemmStart + blockIdx.x;
        if (gb < nbTot)
            gemm_body(gb, sh, A1, W1, b1, C1, M1, A2, W2, b2, C2, M2, K, doRelu, nb1);
        return;
    }
    int cb = blockIdx.x - nGemm;
    int base = (cb * 256 + tid) * 4;
    if (base >= NE) return;

    int4 s4 = *(const int4*)(esrc + base);
    int4 d4 = *(const int4*)(edst + base);
    if (stage == 1) {
        atomicAdd(&g_ocnt[s4.x], 1); atomicAdd(&g_icnt[d4.x], 1);
        atomicAdd(&g_ocnt[s4.y], 1); atomicAdd(&g_icnt[d4.y], 1);
        atomicAdd(&g_ocnt[s4.z], 1); atomicAdd(&g_icnt[d4.z], 1);
        atomicAdd(&g_ocnt[s4.w], 1); atomicAdd(&g_icnt[d4.w], 1);
    } else {
        g_csrc[atomicAdd(&g_cur[d4.x], 1)] = s4.x;
        g_csrc[atomicAdd(&g_cur[d4.y], 1)] = s4.y;
        g_csrc[atomicAdd(&g_cur[d4.z], 1)] = s4.z;
        g_csrc[atomicAdd(&g_cur[d4.w], 1)] = s4.w;
    }
}

// ---------------- standalone small kernels ----------------
__global__ void clear_kernel() {
    int i = blockIdx.x * blockDim.x + threadIdx.x;
    if (i < NN) { g_ocnt[i] = 0; g_icnt[i] = 0; }
}

// scan1: 256 threads, 4 elems each (1024 per block), warp-shuffle scan
__global__ void scan1_kernel() {
    __shared__ int wsum[8];
    int tid = threadIdx.x;
    int base = blockIdx.x * 1024 + tid * 4;
    int v0 = (base + 0 < NN) ? g_icnt[base + 0] : 0;
    int v1 = (base + 1 < NN) ? g_icnt[base + 1] : 0;
    int v2 = (base + 2 < NN) ? g_icnt[base + 2] : 0;
    int v3 = (base + 3 < NN) ? g_icnt[base + 3] : 0;
    int s1 = v0, s2 = v0 + v1, s3 = v0 + v1 + v2, s = s3 + v3;
    int lane = tid & 31, wp = tid >> 5;
    int incl = s;
#pragma unroll
    for (int o = 1; o < 32; o <<= 1) {
        int n = __shfl_up_sync(0xffffffffu, incl, o);
        if (lane >= o) incl += n;
    }
    if (lane == 31) wsum[wp] = incl;
    __syncthreads();
    int wbase = 0;
    for (int k = 0; k < wp; k++) wbase += wsum[k];
    int et = wbase + incl - s;
    if (base + 0 < NN) g_off[base + 0] = et;
    if (base + 1 < NN) g_off[base + 1] = et + s1;
    if (base + 2 < NN) g_off[base + 2] = et + s2;
    if (base + 3 < NN) g_off[base + 3] = et + s3;
    if (tid == 255) g_bsum[blockIdx.x] = wbase + incl;
}

__global__ void scan2_kernel() {
    __shared__ int wsum[4];
    int tid = threadIdx.x;
    int v = (tid < SCAN_NBLK) ? g_bsum[tid] : 0;
    int lane = tid & 31, wp = tid >> 5;
    int incl = v;
#pragma unroll
    for (int o = 1; o < 32; o <<= 1) {
        int n = __shfl_up_sync(0xffffffffu, incl, o);
        if (lane >= o) incl += n;
    }
    if (lane == 31) wsum[wp] = incl;
    __syncthreads();
    int wbase = 0;
    for (int k = 0; k < wp; k++) wbase += wsum[k];
    if (tid < SCAN_NBLK) g_boff[tid] = wbase + incl - v;
}

__global__ void scan3_kernel() {
    int i = blockIdx.x * blockDim.x + threadIdx.x;
    if (i < NN) {
        int o = g_off[i] + g_boff[i >> 10];
        g_off[i] = o;
        g_cur[i] = o;
        g_onorm[i]  = rsqrtf(fmaxf((float)g_ocnt[i], 1.0f));
        g_innorm[i] = rsqrtf(fmaxf((float)g_icnt[i], 1.0f));
    }
}

// ---------------- plain dual GEMM (second GEMM pass) ----------------
__global__ void __launch_bounds__(256, 4) gemm_dual(
    const float* __restrict__ A1, const float* __restrict__ W1, const float* __restrict__ b1,
    float* __restrict__ C1, int M1,
    const float* __restrict__ A2, const float* __restrict__ W2, const float* __restrict__ b2,
    float* __restrict__ C2, int M2,
    int K, int doRelu, int nb1)
{
    __shared__ char sh[24576];
    gemm_body(blockIdx.x, sh, A1, W1, b1, C1, M1, A2, W2, b2, C2, M2, K, doRelu, nb1);
}

// ---------------- GCN layer 1: gather (warp per node) ----------------
__global__ void gather1_kernel() {
    int gw = (blockIdx.x * blockDim.x + threadIdx.x) >> 5;
    int lane = threadIdx.x & 31;
    if (gw >= NN) return;
    int start = g_off[gw];
    int deg = g_icnt[gw];
    float a0 = 0.f, a1 = 0.f;
    for (int j0 = 0; j0 < deg; j0 += 32) {
        int n = min(32, deg - j0);
        int idx = 0; float w = 0.f;
        if (lane < n) { idx = g_csrc[start + j0 + lane]; w = g_onorm[idx]; }
#pragma unroll 4
        for (int jj = 0; jj < n; jj++) {
            int   s  = __shfl_sync(0xffffffffu, idx, jj);
            float wv = __shfl_sync(0xffffffffu, w, jj);
            const float* r = g_e0 + (size_t)s * 64;
            a0 += wv * r[lane];
            a1 += wv * r[lane + 32];
        }
    }
    float inn = g_innorm[gw];
    g_agg0[(size_t)gw * 64 + lane]      = a0 * inn;
    g_agg0[(size_t)gw * 64 + lane + 32] = a1 * inn;
}

// ---------------- GCN layer 2 + final combine fused ----------------
__global__ void gather2_final_kernel(const float* __restrict__ side, float* __restrict__ out) {
    int gw = (blockIdx.x * blockDim.x + threadIdx.x) >> 5;
    int lane = threadIdx.x & 31;
    if (gw >= NN) return;
    int start = g_off[gw];
    int deg = g_icnt[gw];
    float a0 = 0.f, a1 = 0.f;
    for (int j0 = 0; j0 < deg; j0 += 32) {
        int n = min(32, deg - j0);
        int idx = 0; float w = 0.f;
        if (lane < n) { idx = g_csrc[start + j0 + lane]; w = g_onorm[idx]; }
#pragma unroll 4
        for (int jj = 0; jj < n; jj++) {
            int   s  = __shfl_sync(0xffffffffu, idx, jj);
            float wv = __shfl_sync(0xffffffffu, w, jj);
            const float* r = g_agg0 + (size_t)s * 64;
            a0 += wv * r[lane];
            a1 += wv * r[lane + 32];
        }
    }
    float inn3 = g_innorm[gw] * (1.0f / 3.0f);
    size_t base = (size_t)gw * 64;
    float r0v = g_e0[base + lane]      + 0.5f * g_agg0[base + lane]      + inn3 * a0;
    float r1v = g_e0[base + lane + 32] + 0.5f * g_agg0[base + lane + 32] + inn3 * a1;
    if (gw >= NU) {
        size_t sb = (size_t)(gw - NU) * 64;
        r0v += side[sb + lane];
        r1v += side[sb + lane + 32];
    }
    out[base + lane]      = r0v;
    out[base + lane + 32] = r1v;
}

// ---------------- decode epilogue ----------------
__global__ void decode_kernel(const float* __restrict__ Tf, const float* __restrict__ Tcf,
                              const float* __restrict__ W1, const float* __restrict__ W2,
                              const int* __restrict__ userId, const int* __restrict__ posId,
                              const int* __restrict__ negId,
                              float* __restrict__ of, float* __restrict__ ocf) {
    __shared__ float w2s[64];
    __shared__ float w1l[64];
    int t = threadIdx.x;
    if (t < 64) {
        w2s[t] = W2[t];
        w1l[t] = W1[128 * 64 + t];
    }
    __syncthreads();

    int warp = t >> 5, lane = t & 31;
    int pair = blockIdx.x * 8 + warp;
    if (pair >= NP) return;

    int u  = userId[pair];
    int p  = posId[pair];
    int ng = negId[pair];

    float u0 = g_xu[(size_t)u * 64 + lane],   u1 = g_xu[(size_t)u * 64 + lane + 32];
    float p0 = g_xi[(size_t)p * 64 + lane],   p1 = g_xi[(size_t)p * 64 + lane + 32];
    float n0 = g_xi[(size_t)ng * 64 + lane],  n1 = g_xi[(size_t)ng * 64 + lane + 32];
    float wl0 = w1l[lane], wl1 = w1l[lane + 32];
    float w20 = w2s[lane], w21 = w2s[lane + 32];

    float tfp = Tf[pair],  tfn = Tf[pair + NP];
    float tcp = Tcf[pair], tcn = Tcf[pair + NP];

    auto combo = [&](float j0, float j1, float T) -> float {
        float x0 = u0 + j0 + T * wl0;
        float x1 = u1 + j1 + T * wl1;
        float e0 = x0 > 0.f ? x0 : (expf(x0) - 1.0f);
        float e1 = x1 > 0.f ? x1 : (expf(x1) - 1.0f);
        float s = e0 * w20 + e1 * w21;
        s += __shfl_down_sync(0xffffffffu, s, 16);
        s += __shfl_down_sync(0xffffffffu, s, 8);
        s += __shfl_down_sync(0xffffffffu, s, 4);
        s += __shfl_down_sync(0xffffffffu, s, 2);
        s += __shfl_down_sync(0xffffffffu, s, 1);
        return s;
    };

    float rf_p = combo(p0, p1, tfp);
    float rf_n = combo(n0, n1, tfn);
    float rc_p = combo(p0, p1, tcp);
    float rc_n = combo(n0, n1, tcn);

    if (lane == 0) {
        of[pair]       = rf_p;
        of[pair + NP]  = rf_n;
        ocf[pair]      = rc_p;
        ocf[pair + NP] = rc_n;
    }
}

// ---------------- launch ----------------
extern "C" void kernel_launch(void* const* d_in, const int* in_sizes, int n_in,
                              void* d_out, int out_size) {
    const float* userF = (const float*)d_in[0];
    const float* itemF = (const float*)d_in[1];
    const float* side  = (const float*)d_in[2];
    const float* Tf    = (const float*)d_in[3];
    const float* Tcf   = (const float*)d_in[4];
    const float* Wu    = (const float*)d_in[5];
    const float* bu    = (const float*)d_in[6];
    const float* Wi    = (const float*)d_in[7];
    const float* bi    = (const float*)d_in[8];
    const float* W1    = (const float*)d_in[9];
    const float* b1    = (const float*)d_in[10];
    const float* W2    = (const float*)d_in[11];
    const int* esrc    = (const int*)d_in[12];
    const int* edst    = (const int*)d_in[13];
    const int* userId  = (const int*)d_in[14];
    const int* posId   = (const int*)d_in[15];
    const int* negId   = (const int*)d_in[16];

    float* out   = (float*)d_out;
    float* outI  = out + (size_t)NU * H;
    float* outLF = out + (size_t)NN * H;
    float* outLC = outLF + 2 * NP;

    float *pe0, *pxu, *pxi;
    cudaGetSymbolAddress((void**)&pe0, g_e0);
    cudaGetSymbolAddress((void**)&pxu, g_xu);
    cudaGetSymbolAddress((void**)&pxi, g_xi);

    int nb1 = (NU + 127) / 128;            // 391
    int nb2 = (NI + 127) / 128;            // 391
    int nbTot = nb1 + nb2;                 // 782
    int edgeBlocks = (NE / 4 + 255) / 256; // 1563

    // clear counters
    clear_kernel<<<(NN + 255) / 256, 256>>>();

    // degree stage fused with first 300 GEMM blocks
    csr_gemm_kernel<<<300 + edgeBlocks, 256>>>(
        1, 300, 0, esrc, edst,
        userF, Wu, bu, pe0, NU,
        itemF, Wi, bi, pe0 + (size_t)NU * H, NI,
        128, 1, nb1, nbTot);

    // scans (cheap, standalone)
    scan1_kernel<<<SCAN_NBLK, 256>>>();
    scan2_kernel<<<1, 128>>>();
    scan3_kernel<<<(NN + 255) / 256, 256>>>();

    // fill stage fused with remaining 482 GEMM blocks
    csr_gemm_kernel<<<482 + edgeBlocks, 256>>>(
        5, 482, 300, esrc, edst,
        userF, Wu, bu, pe0, NU,
        itemF, Wi, bi, pe0 + (size_t)NU * H, NI,
        128, 1, nb1, nbTot);

    // GCN layers
    gather1_kernel<<<(NN * 32 + 255) / 256, 256>>>();
    gather2_final_kernel<<<(NN * 32 + 255) / 256, 256>>>(side, out);

    // per-node decode transforms
    gemm_dual<<<nbTot, 256>>>(out,  W1,           b1,      pxu, NU,
                              outI, W1 + 64 * 64, nullptr, pxi, NI,
                              64, 0, nb1);

    // decode epilogue
    decode_kernel<<<(NP + 7) / 8, 256>>>(Tf, Tcf, W1, W2, userId, posId, negId, outLF, outLC);
}

// round 7
// speedup vs baseline: 1.0939x; 1.0175x over previous
#include <cuda_runtime.h>
#include <math.h>

#define NU 50000
#define NI 50000
#define NN 100000
#define NE 1600000
#define NP 200000
#define H  64
#define SCAN_NBLK ((NN + 1023) / 1024)   // 98

// ---------------- device scratch ----------------
__device__ int   g_ocnt[NN];
__device__ int   g_icnt[NN];
__device__ float g_onorm[NN];
__device__ float g_innorm[NN];
__device__ int   g_off[NN];
__device__ int   g_cur[NN];
__device__ int   g_bsum[SCAN_NBLK];
__device__ int   g_csrc[NE];
__device__ float g_e0[(size_t)NN * H];
__device__ float g_agg0[(size_t)NN * H];    // layer-1 "embeddings"
__device__ float g_agg0s[(size_t)NN * H];   // agg0 * out_norm (prescaled for layer 2)
__device__ float g_xu[(size_t)NU * H];
__device__ float g_xi[(size_t)NI * H];

// ---------------- lean GEMM body: 24.6KB smem, double-buffered A and W ----------------
__device__ __forceinline__ void gemm_body(
    int gb, char* sh,
    const float* __restrict__ A1, const float* __restrict__ W1, const float* __restrict__ b1,
    float* __restrict__ C1, int M1,
    const float* __restrict__ A2, const float* __restrict__ W2, const float* __restrict__ b2,
    float* __restrict__ C2, int M2,
    int K, int doRelu, int nb1)
{
    float (*Ws)[16][64]  = (float(*)[16][64])sh;
    float (*As)[16][128] = (float(*)[16][128])(sh + 8192);

    const float* A; const float* W; const float* bias; float* C; int M, bm0;
    if (gb < nb1) {
        A = A1; W = W1; bias = b1; C = C1; M = M1; bm0 = gb * 128;
    } else {
        A = A2; W = W2; bias = b2; C = C2; M = M2; bm0 = (gb - nb1) * 128;
    }

    int t = threadIdx.x;
    int wk = t >> 4;
    int wc = t & 15;
    int lrow = t >> 1;
    int lq = (t & 1) * 8;
    int row = bm0 + lrow;
    bool rv = row < M;
    const float* Ar = A + (size_t)row * K;

    float4 p0 = make_float4(0.f, 0.f, 0.f, 0.f), p1 = p0, wv = p0;

#define FETCHA(k0) do { \
    if (rv) { p0 = *(const float4*)(Ar + (k0) + lq); p1 = *(const float4*)(Ar + (k0) + lq + 4); } \
} while (0)
#define FETCHW(k0) do { wv = *(const float4*)(W + (size_t)((k0) + wk) * 64 + wc * 4); } while (0)
#define STAGEA(buf) do { \
    As[buf][lq + 0][lrow] = p0.x; As[buf][lq + 1][lrow] = p0.y; \
    As[buf][lq + 2][lrow] = p0.z; As[buf][lq + 3][lrow] = p0.w; \
    As[buf][lq + 4][lrow] = p1.x; As[buf][lq + 5][lrow] = p1.y; \
    As[buf][lq + 6][lrow] = p1.z; As[buf][lq + 7][lrow] = p1.w; \
} while (0)
#define STAGEW(buf) do { *(float4*)&Ws[buf][wk][wc * 4] = wv; } while (0)

    FETCHA(0); FETCHW(0);
    STAGEA(0); STAGEW(0);
    __syncthreads();

    float acc[8][4];
#pragma unroll
    for (int i = 0; i < 8; i++)
#pragma unroll
        for (int j = 0; j < 4; j++) acc[i][j] = 0.f;

    int tx = t & 15;
    int ty = t >> 4;
    int nt = K >> 4;

    for (int tile = 0; tile < nt; tile++) {
        int buf = tile & 1;
        if (tile + 1 < nt) { FETCHA((tile + 1) << 4); FETCHW((tile + 1) << 4); }

#pragma unroll
        for (int k = 0; k < 16; k++) {
            float4 b  = *(const float4*)&Ws[buf][k][tx * 4];
            float4 x0 = *(const float4*)&As[buf][k][ty * 8];
            float4 x1 = *(const float4*)&As[buf][k][ty * 8 + 4];
            acc[0][0] += x0.x * b.x; acc[0][1] += x0.x * b.y; acc[0][2] += x0.x * b.z; acc[0][3] += x0.x * b.w;
            acc[1][0] += x0.y * b.x; acc[1][1] += x0.y * b.y; acc[1][2] += x0.y * b.z; acc[1][3] += x0.y * b.w;
            acc[2][0] += x0.z * b.x; acc[2][1] += x0.z * b.y; acc[2][2] += x0.z * b.z; acc[2][3] += x0.z * b.w;
            acc[3][0] += x0.w * b.x; acc[3][1] += x0.w * b.y; acc[3][2] += x0.w * b.z; acc[3][3] += x0.w * b.w;
            acc[4][0] += x1.x * b.x; acc[4][1] += x1.x * b.y; acc[4][2] += x1.x * b.z; acc[4][3] += x1.x * b.w;
            acc[5][0] += x1.y * b.x; acc[5][1] += x1.y * b.y; acc[5][2] += x1.y * b.z; acc[5][3] += x1.y * b.w;
            acc[6][0] += x1.z * b.x; acc[6][1] += x1.z * b.y; acc[6][2] += x1.z * b.z; acc[6][3] += x1.z * b.w;
            acc[7][0] += x1.w * b.x; acc[7][1] += x1.w * b.y; acc[7][2] += x1.w * b.z; acc[7][3] += x1.w * b.w;
        }

        if (tile + 1 < nt) {
            __syncthreads();
            STAGEA((tile + 1) & 1);
            STAGEW((tile + 1) & 1);
            __syncthreads();
        }
    }

    float bvals[4] = {0.f, 0.f, 0.f, 0.f};
    if (bias) {
#pragma unroll
        for (int j = 0; j < 4; j++) bvals[j] = bias[tx * 4 + j];
    }

#pragma unroll
    for (int r = 0; r < 8; r++) {
        int orow = bm0 + ty * 8 + r;
        if (orow < M) {
            float4 v;
            v.x = acc[r][0] + bvals[0];
            v.y = acc[r][1] + bvals[1];
            v.z = acc[r][2] + bvals[2];
            v.w = acc[r][3] + bvals[3];
            if (doRelu) {
                v.x = fmaxf(v.x, 0.f); v.y = fmaxf(v.y, 0.f);
                v.z = fmaxf(v.z, 0.f); v.w = fmaxf(v.w, 0.f);
            }
            *(float4*)(C + (size_t)orow * 64 + tx * 4) = v;
        }
    }
#undef FETCHA
#undef FETCHW
#undef STAGEA
#undef STAGEW
}

// ---------------- fused edge-stage + GEMM-chunk co-kernel ----------------
__global__ void __launch_bounds__(256, 4) csr_gemm_kernel(
    int stage, int nGemm, int gemmStart,
    const int* __restrict__ esrc, const int* __restrict__ edst,
    const float* __restrict__ A1, const float* __restrict__ W1, const float* __restrict__ b1,
    float* __restrict__ C1, int M1,
    const float* __restrict__ A2, const float* __restrict__ W2, const float* __restrict__ b2,
    float* __restrict__ C2, int M2,
    int K, int doRelu, int nb1, int nbTot)
{
    __shared__ char sh[24576];
    int tid = threadIdx.x;

    if ((int)blockIdx.x < nGemm) {
        int gb = gemmStart + blockIdx.x;
        if (gb < nbTot)
            gemm_body(gb, sh, A1, W1, b1, C1, M1, A2, W2, b2, C2, M2, K, doRelu, nb1);
        return;
    }
    int cb = blockIdx.x - nGemm;
    int base = (cb * 256 + tid) * 4;
    if (base >= NE) return;

    int4 s4 = *(const int4*)(esrc + base);
    int4 d4 = *(const int4*)(edst + base);
    if (stage == 1) {
        atomicAdd(&g_ocnt[s4.x], 1); atomicAdd(&g_icnt[d4.x], 1);
        atomicAdd(&g_ocnt[s4.y], 1); atomicAdd(&g_icnt[d4.y], 1);
        atomicAdd(&g_ocnt[s4.z], 1); atomicAdd(&g_icnt[d4.z], 1);
        atomicAdd(&g_ocnt[s4.w], 1); atomicAdd(&g_icnt[d4.w], 1);
    } else {
        g_csrc[atomicAdd(&g_cur[d4.x], 1)] = s4.x;
        g_csrc[atomicAdd(&g_cur[d4.y], 1)] = s4.y;
        g_csrc[atomicAdd(&g_cur[d4.z], 1)] = s4.z;
        g_csrc[atomicAdd(&g_cur[d4.w], 1)] = s4.w;
    }
}

// ---------------- standalone small kernels ----------------
__global__ void clear_kernel() {
    int i = blockIdx.x * blockDim.x + threadIdx.x;
    if (i < NN) { g_ocnt[i] = 0; g_icnt[i] = 0; }
}

// scan1: 256 threads, 4 elems each (1024/block), warp-shuffle scan; writes per-block sums
__global__ void scan1_kernel() {
    __shared__ int wsum[8];
    int tid = threadIdx.x;
    int base = blockIdx.x * 1024 + tid * 4;
    int v0 = (base + 0 < NN) ? g_icnt[base + 0] : 0;
    int v1 = (base + 1 < NN) ? g_icnt[base + 1] : 0;
    int v2 = (base + 2 < NN) ? g_icnt[base + 2] : 0;
    int v3 = (base + 3 < NN) ? g_icnt[base + 3] : 0;
    int s1 = v0, s2 = v0 + v1, s3 = v0 + v1 + v2, s = s3 + v3;
    int lane = tid & 31, wp = tid >> 5;
    int incl = s;
#pragma unroll
    for (int o = 1; o < 32; o <<= 1) {
        int n = __shfl_up_sync(0xffffffffu, incl, o);
        if (lane >= o) incl += n;
    }
    if (lane == 31) wsum[wp] = incl;
    __syncthreads();
    int wbase = 0;
    for (int k = 0; k < wp; k++) wbase += wsum[k];
    int et = wbase + incl - s;
    if (base + 0 < NN) g_off[base + 0] = et;
    if (base + 1 < NN) g_off[base + 1] = et + s1;
    if (base + 2 < NN) g_off[base + 2] = et + s2;
    if (base + 3 < NN) g_off[base + 3] = et + s3;
    if (tid == 255) g_bsum[blockIdx.x] = wbase + incl;
}

// scan3: per-block re-derives global block prefix from g_bsum, finalizes offsets + norms
__global__ void scan3_kernel() {
    __shared__ int sboff[SCAN_NBLK];
    __shared__ int wsum[4];
    int tid = threadIdx.x;
    // block-local scan of the 98 block sums (all blocks redo this tiny scan)
    if (tid < 128) {
        int v = (tid < SCAN_NBLK) ? g_bsum[tid] : 0;
        int lane = tid & 31, wp = tid >> 5;
        int incl = v;
#pragma unroll
        for (int o = 1; o < 32; o <<= 1) {
            int n = __shfl_up_sync(0xffffffffu, incl, o);
            if (lane >= o) incl += n;
        }
        if (lane == 31) wsum[wp] = incl;
        __syncthreads();
        int wbase = 0;
        for (int k = 0; k < wp; k++) wbase += wsum[k];
        if (tid < SCAN_NBLK) sboff[tid] = wbase + incl - v;
    } else {
        __syncthreads();
    }
    __syncthreads();
    int i = blockIdx.x * blockDim.x + tid;
    if (i < NN) {
        int o = g_off[i] + sboff[i >> 10];
        g_off[i] = o;
        g_cur[i] = o;
        g_onorm[i]  = rsqrtf(fmaxf((float)g_ocnt[i], 1.0f));
        g_innorm[i] = rsqrtf(fmaxf((float)g_icnt[i], 1.0f));
    }
}

// ---------------- plain dual GEMM ----------------
__global__ void __launch_bounds__(256, 4) gemm_dual(
    const float* __restrict__ A1, const float* __restrict__ W1, const float* __restrict__ b1,
    float* __restrict__ C1, int M1,
    const float* __restrict__ A2, const float* __restrict__ W2, const float* __restrict__ b2,
    float* __restrict__ C2, int M2,
    int K, int doRelu, int nb1)
{
    __shared__ char sh[24576];
    gemm_body(blockIdx.x, sh, A1, W1, b1, C1, M1, A2, W2, b2, C2, M2, K, doRelu, nb1);
}

// ---------------- GCN layer 1: gather (warp/node, float2 rows) ----------------
// agg0 = inn * sum(e0[src]*onorm[src]);  agg0s = agg0 * onorm (prescaled for layer 2)
__global__ void gather1_kernel() {
    int gw = (blockIdx.x * blockDim.x + threadIdx.x) >> 5;
    int lane = threadIdx.x & 31;
    if (gw >= NN) return;
    int start = g_off[gw];
    int deg = g_icnt[gw];
    float a0 = 0.f, a1 = 0.f;
    int nfull = deg & ~31;
    for (int j0 = 0; j0 < nfull; j0 += 32) {
        int idx = g_csrc[start + j0 + lane];
        float w = g_onorm[idx];
#pragma unroll
        for (int jj = 0; jj < 32; jj++) {
            int   s  = __shfl_sync(0xffffffffu, idx, jj);
            float wv = __shfl_sync(0xffffffffu, w, jj);
            float2 r = *(const float2*)(g_e0 + (size_t)s * 64 + 2 * lane);
            a0 += wv * r.x;
            a1 += wv * r.y;
        }
    }
    int rem = deg - nfull;
    if (rem) {
        int idx = 0; float w = 0.f;
        if (lane < rem) { idx = g_csrc[start + nfull + lane]; w = g_onorm[idx]; }
        for (int jj = 0; jj < rem; jj++) {
            int   s  = __shfl_sync(0xffffffffu, idx, jj);
            float wv = __shfl_sync(0xffffffffu, w, jj);
            float2 r = *(const float2*)(g_e0 + (size_t)s * 64 + 2 * lane);
            a0 += wv * r.x;
            a1 += wv * r.y;
        }
    }
    float inn = g_innorm[gw];
    float onm = g_onorm[gw];
    float2 v  = make_float2(a0 * inn, a1 * inn);
    float2 vs = make_float2(v.x * onm, v.y * onm);
    *(float2*)(g_agg0  + (size_t)gw * 64 + 2 * lane) = v;
    *(float2*)(g_agg0s + (size_t)gw * 64 + 2 * lane) = vs;
}

// ---------------- GCN layer 2 + final combine (prescaled input: no w shuffle) ----------------
__global__ void gather2_final_kernel(const float* __restrict__ side, float* __restrict__ out) {
    int gw = (blockIdx.x * blockDim.x + threadIdx.x) >> 5;
    int lane = threadIdx.x & 31;
    if (gw >= NN) return;
    int start = g_off[gw];
    int deg = g_icnt[gw];
    float a0 = 0.f, a1 = 0.f;
    int nfull = deg & ~31;
    for (int j0 = 0; j0 < nfull; j0 += 32) {
        int idx = g_csrc[start + j0 + lane];
#pragma unroll
        for (int jj = 0; jj < 32; jj++) {
            int s = __shfl_sync(0xffffffffu, idx, jj);
            float2 r = *(const float2*)(g_agg0s + (size_t)s * 64 + 2 * lane);
            a0 += r.x;
            a1 += r.y;
        }
    }
    int rem = deg - nfull;
    if (rem) {
        int idx = 0;
        if (lane < rem) idx = g_csrc[start + nfull + lane];
        for (int jj = 0; jj < rem; jj++) {
            int s = __shfl_sync(0xffffffffu, idx, jj);
            float2 r = *(const float2*)(g_agg0s + (size_t)s * 64 + 2 * lane);
            a0 += r.x;
            a1 += r.y;
        }
    }
    float inn3 = g_innorm[gw] * (1.0f / 3.0f);
    size_t base = (size_t)gw * 64 + 2 * lane;
    float2 e  = *(const float2*)(g_e0 + base);
    float2 m  = *(const float2*)(g_agg0 + base);
    float r0v = e.x + 0.5f * m.x + inn3 * a0;
    float r1v = e.y + 0.5f * m.y + inn3 * a1;
    if (gw >= NU) {
        float2 sd = *(const float2*)(side + (size_t)(gw - NU) * 64 + 2 * lane);
        r0v += sd.x;
        r1v += sd.y;
    }
    *(float2*)(out + base) = make_float2(r0v, r1v);
}

// ---------------- decode epilogue (float2 gathers) ----------------
__global__ void decode_kernel(const float* __restrict__ Tf, const float* __restrict__ Tcf,
                              const float* __restrict__ W1, const float* __restrict__ W2,
                              const int* __restrict__ userId, const int* __restrict__ posId,
                              const int* __restrict__ negId,
                              float* __restrict__ of, float* __restrict__ ocf) {
    __shared__ float w2s[64];
    __shared__ float w1l[64];
    int t = threadIdx.x;
    if (t < 64) {
        w2s[t] = W2[t];
        w1l[t] = W1[128 * 64 + t];
    }
    __syncthreads();

    int warp = t >> 5, lane = t & 31;
    int pair = blockIdx.x * 8 + warp;
    if (pair >= NP) return;

    int u  = userId[pair];
    int p  = posId[pair];
    int ng = negId[pair];

    float2 uv = *(const float2*)(g_xu + (size_t)u * 64 + 2 * lane);
    float2 pv = *(const float2*)(g_xi + (size_t)p * 64 + 2 * lane);
    float2 nv = *(const float2*)(g_xi + (size_t)ng * 64 + 2 * lane);
    float2 wl = *(const float2*)(w1l + 2 * lane);
    float2 w2 = *(const float2*)(w2s + 2 * lane);

    float tfp = Tf[pair],  tfn = Tf[pair + NP];
    float tcp = Tcf[pair], tcn = Tcf[pair + NP];

    auto combo = [&](float j0, float j1, float T) -> float {
        float x0 = uv.x + j0 + T * wl.x;
        float x1 = uv.y + j1 + T * wl.y;
        float e0 = x0 > 0.f ? x0 : (expf(x0) - 1.0f);
        float e1 = x1 > 0.f ? x1 : (expf(x1) - 1.0f);
        float s = e0 * w2.x + e1 * w2.y;
        s += __shfl_down_sync(0xffffffffu, s, 16);
        s += __shfl_down_sync(0xffffffffu, s, 8);
        s += __shfl_down_sync(0xffffffffu, s, 4);
        s += __shfl_down_sync(0xffffffffu, s, 2);
        s += __shfl_down_sync(0xffffffffu, s, 1);
        return s;
    };

    float rf_p = combo(pv.x, pv.y, tfp);
    float rf_n = combo(nv.x, nv.y, tfn);
    float rc_p = combo(pv.x, pv.y, tcp);
    float rc_n = combo(nv.x, nv.y, tcn);

    if (lane == 0) {
        of[pair]       = rf_p;
        of[pair + NP]  = rf_n;
        ocf[pair]      = rc_p;
        ocf[pair + NP] = rc_n;
    }
}

// ---------------- launch ----------------
extern "C" void kernel_launch(void* const* d_in, const int* in_sizes, int n_in,
                              void* d_out, int out_size) {
    const float* userF = (const float*)d_in[0];
    const float* itemF = (const float*)d_in[1];
    const float* side  = (const float*)d_in[2];
    const float* Tf    = (const float*)d_in[3];
    const float* Tcf   = (const float*)d_in[4];
    const float* Wu    = (const float*)d_in[5];
    const float* bu    = (const float*)d_in[6];
    const float* Wi    = (const float*)d_in[7];
    const float* bi    = (const float*)d_in[8];
    const float* W1    = (const float*)d_in[9];
    const float* b1    = (const float*)d_in[10];
    const float* W2    = (const float*)d_in[11];
    const int* esrc    = (const int*)d_in[12];
    const int* edst    = (const int*)d_in[13];
    const int* userId  = (const int*)d_in[14];
    const int* posId   = (const int*)d_in[15];
    const int* negId   = (const int*)d_in[16];

    float* out   = (float*)d_out;
    float* outI  = out + (size_t)NU * H;
    float* outLF = out + (size_t)NN * H;
    float* outLC = outLF + 2 * NP;

    float *pe0, *pxu, *pxi;
    cudaGetSymbolAddress((void**)&pe0, g_e0);
    cudaGetSymbolAddress((void**)&pxu, g_xu);
    cudaGetSymbolAddress((void**)&pxi, g_xi);

    int nb1 = (NU + 127) / 128;            // 391
    int nb2 = (NI + 127) / 128;            // 391
    int nbTot = nb1 + nb2;                 // 782
    int edgeBlocks = (NE / 4 + 255) / 256; // 1563

    clear_kernel<<<(NN + 255) / 256, 256>>>();

    // degree stage fused with first 300 GEMM blocks
    csr_gemm_kernel<<<300 + edgeBlocks, 256>>>(
        1, 300, 0, esrc, edst,
        userF, Wu, bu, pe0, NU,
        itemF, Wi, bi, pe0 + (size_t)NU * H, NI,
        128, 1, nb1, nbTot);

    scan1_kernel<<<SCAN_NBLK, 256>>>();
    scan3_kernel<<<(NN + 255) / 256, 256>>>();

    // fill stage fused with remaining 482 GEMM blocks
    csr_gemm_kernel<<<482 + edgeBlocks, 256>>>(
        5, 482, 300, esrc, edst,
        userF, Wu, bu, pe0, NU,
        itemF, Wi, bi, pe0 + (size_t)NU * H, NI,
        128, 1, nb1, nbTot);

    // GCN layers
    gather1_kernel<<<(NN * 32 + 255) / 256, 256>>>();
    gather2_final_kernel<<<(NN * 32 + 255) / 256, 256>>>(side, out);

    // per-node decode transforms
    gemm_dual<<<nbTot, 256>>>(out,  W1,           b1,      pxu, NU,
                              outI, W1 + 64 * 64, nullptr, pxi, NI,
                              64, 0, nb1);

    // decode epilogue
    decode_kernel<<<(NP + 7) / 8, 256>>>(Tf, Tcf, W1, W2, userId, posId, negId, outLF, outLC);
}